// round 1
// baseline (speedup 1.0000x reference)
#include <cuda_runtime.h>
#include <math.h>

#define NQ 32
#define NBLOCKS 512
#define TPB 256

// ---- 32-point Gauss-Legendre (positive half; symmetric) ----
__device__ constexpr float GLX16[16] = {
    0.04830766568773832f, 0.14447196158279649f, 0.23928736225213707f, 0.33186860228212765f,
    0.42135127613063535f, 0.50689990893222939f, 0.58771575724076233f, 0.66304426693021520f,
    0.73218211874028968f, 0.79448379596794241f, 0.84936761373256997f, 0.89632115576605212f,
    0.93490607593773969f, 0.96476225558750643f, 0.98561151154526840f, 0.99726386184948156f};
__device__ constexpr float GLW16[16] = {
    0.09654008851472781f, 0.09563872007927486f, 0.09384439908080456f, 0.09117387869576388f,
    0.08765209300440381f, 0.08331192422694676f, 0.07819389578707031f, 0.07234579410884851f,
    0.06582222277636185f, 0.05868409347853555f, 0.05099805926237618f, 0.04283589802222668f,
    0.03427386291302143f, 0.02539206530926206f, 0.01627439473090567f, 0.00701861000947010f};

// hx = (x+1)/2 for node index q in [0,32)  (first 16 negative nodes, then positive)
__device__ constexpr float hx_of(int q) {
    return (q < 16) ? 0.5f * (1.0f - GLX16[15 - q]) : 0.5f * (1.0f + GLX16[q - 16]);
}
__device__ constexpr float gw_of(int q) {
    return (q < 16) ? GLW16[15 - q] : GLW16[q - 16];
}

// runtime-derived constants (written by setup_kernel, read by loss_kernel)
__device__ float d_c0[NQ];   // log2e / (2(1-r_q^2))
__device__ float d_lw[NQ];   // log2( w_q * |rho|/2 / (2pi * sqrt(1-r_q^2)) )
__device__ float d_sc[13];   // M00,M01,M10,M11, i00,i01s,i11, inv_s1g,inv_s2g, sgn, inv_sig1,inv_sig2, 2*rho
__device__ double d_part[NBLOCKS];

__device__ __forceinline__ float ex2f(float x) {
    float y;
    asm("ex2.approx.ftz.f32 %0, %1;" : "=f"(y) : "f"(x));
    return y;
}

__global__ void setup_kernel(const float* __restrict__ g12, const float* __restrict__ g34,
                             const float* __restrict__ g3412, const float* __restrict__ s1,
                             const float* __restrict__ s2) {
    if (threadIdx.x != 0 || blockIdx.x != 0) return;
    double a = g12[0], b = g12[1], c = g12[2], d = g12[3];
    double det = a * d - b * c;
    double i00 = d / det, i01 = -b / det, i10 = -c / det, i11 = a / det;
    double t0 = g3412[0], t1 = g3412[1], t2 = g3412[2], t3 = g3412[3];
    double M00 = t0 * i00 + t1 * i10, M01 = t0 * i01 + t1 * i11;
    double M10 = t2 * i00 + t3 * i10, M11 = t2 * i01 + t3 * i11;
    // gamma_star = gamma34 - M @ gamma3412^T
    double gs00 = (double)g34[0] - (M00 * t0 + M01 * t1);
    double gs01 = (double)g34[1] - (M00 * t2 + M01 * t3);
    double gs11 = (double)g34[3] - (M10 * t2 + M11 * t3);
    double s1g = sqrt(gs00), s2g = sqrt(gs11);
    double rho = gs01 / (s1g * s2g);

    d_sc[0] = (float)M00;  d_sc[1] = (float)M01;
    d_sc[2] = (float)M10;  d_sc[3] = (float)M11;
    d_sc[4] = (float)i00;  d_sc[5] = (float)(i01 + i10);  d_sc[6] = (float)i11;
    d_sc[7] = (float)(1.0 / s1g);  d_sc[8] = (float)(1.0 / s2g);
    d_sc[9] = (rho >= 0.0) ? 1.0f : -1.0f;
    d_sc[10] = (float)(1.0 / (double)s1[0]);
    d_sc[11] = (float)(1.0 / (double)s2[0]);
    d_sc[12] = (float)(2.0 * rho);

    const double L2E = 1.4426950408889634;
    const double TWOPI = 6.283185307179586;
    for (int q = 0; q < NQ; q++) {
        double hx = (double)hx_of(q);
        double w = (double)gw_of(q);
        double r = rho * hx;
        double omr2 = 1.0 - r * r;
        d_c0[q] = (float)(L2E / (2.0 * omr2));
        double amp = w * fabs(rho) * 0.5 / (TWOPI * sqrt(omr2));
        d_lw[q] = (amp > 0.0) ? (float)(log2(amp)) : -1e30f;
    }
}

__global__ __launch_bounds__(TPB) void loss_kernel(const float* __restrict__ yhat,
                                                   const float* __restrict__ yv, int n) {
    const float M00 = d_sc[0], M01 = d_sc[1], M10 = d_sc[2], M11 = d_sc[3];
    const float i00 = d_sc[4], i01s = d_sc[5], i11 = d_sc[6];
    const float inv_s1g = d_sc[7], inv_s2g = d_sc[8], sgn = d_sc[9];
    const float inv_sig1 = d_sc[10], inv_sig2 = d_sc[11], rho2 = d_sc[12];

    float c0r[NQ], lwr[NQ];
#pragma unroll
    for (int q = 0; q < NQ; q++) { c0r[q] = d_c0[q]; lwr[q] = d_lw[q]; }

    const float* p3p = yhat;
    const float* m1p = yhat + n;
    const float* p4p = yhat + 2 * n;
    const float* m2p = yhat + 3 * n;
    const float* l3p = yv;
    const float* r1p = yv + n;
    const float* l4p = yv + 2 * n;
    const float* r2p = yv + 3 * n;

    float tsum = 0.0f;
    const int stride = gridDim.x * blockDim.x;
    for (int i = blockIdx.x * blockDim.x + threadIdx.x; i < n; i += stride) {
        const float p3 = __ldg(p3p + i);
        const float p4 = __ldg(p4p + i);
        const float e1 = (__ldg(r1p + i) - __ldg(m1p + i)) * inv_sig1;
        const float e2 = (__ldg(r2p + i) - __ldg(m2p + i)) * inv_sig2;
        const float l3 = __ldg(l3p + i);
        const float l4 = __ldg(l4p + i);

        const float mu1 = fmaf(M00, e1, M01 * e2);
        const float mu2 = fmaf(M10, e1, M11 * e2);
        const float quad = fmaf(i00 * e1, e1, fmaf(i01s * e1, e2, i11 * e2 * e2));

        const float q3 = normcdfinvf(1.0f - p3);
        const float q4 = normcdfinvf(1.0f - p4);
        const float h = (q3 - mu1) * inv_s1g;
        const float k = (q4 - mu2) * inv_s2g;
        const float P3 = normcdff(h);
        const float P4 = normcdff(k);

        const float mS = -fmaf(h, h, k * k);     // -(h^2+k^2)
        const float HK = rho2 * h * k;           // 2*rho*h*k

        float acc0 = 0.0f, acc1 = 0.0f;
#pragma unroll
        for (int q = 0; q < NQ; q += 2) {
            const float T0 = fmaf(HK, hx_of(q), mS);
            const float T1 = fmaf(HK, hx_of(q + 1), mS);
            const float E0 = fmaf(c0r[q], T0, lwr[q]);
            const float E1 = fmaf(c0r[q + 1], T1, lwr[q + 1]);
            acc0 += ex2f(E0);
            acc1 += ex2f(E1);
        }
        const float B = fmaf(P3, P4, sgn * (acc0 + acc1));   // BVN(h,k;rho)

        const bool b3 = !(l3 < 1.0f);
        const bool b4 = !(l4 < 1.0f);
        const float Ci = b3 ? (b4 ? (1.0f - P3 - P4 + B) : (P4 - B))
                            : (b4 ? (P3 - B) : B);

        tsum += fmaf(-0.5f, quad, logf(fmaxf(Ci, 1e-30f)));
    }

    __shared__ double sd[TPB];
    sd[threadIdx.x] = (double)tsum;
    __syncthreads();
#pragma unroll
    for (int s = TPB / 2; s > 0; s >>= 1) {
        if (threadIdx.x < s) sd[threadIdx.x] += sd[threadIdx.x + s];
        __syncthreads();
    }
    if (threadIdx.x == 0) d_part[blockIdx.x] = sd[0];
}

__global__ void reduce_kernel(float* __restrict__ out) {
    __shared__ double sd[NBLOCKS];
    const int t = threadIdx.x;
    sd[t] = d_part[t];
    __syncthreads();
#pragma unroll
    for (int s = NBLOCKS / 2; s > 0; s >>= 1) {
        if (t < s) sd[t] += sd[t + s];
        __syncthreads();
    }
    if (t == 0) out[0] = (float)(-sd[0]);
}

extern "C" void kernel_launch(void* const* d_in, const int* in_sizes, int n_in,
                              void* d_out, int out_size) {
    const float* yhat = (const float*)d_in[0];
    const float* yv = (const float*)d_in[1];
    const float* g12 = (const float*)d_in[2];
    const float* g34 = (const float*)d_in[3];
    const float* g3412 = (const float*)d_in[4];
    const float* s1 = (const float*)d_in[5];
    const float* s2 = (const float*)d_in[6];
    const int n = in_sizes[0] / 4;

    setup_kernel<<<1, 32>>>(g12, g34, g3412, s1, s2);
    loss_kernel<<<NBLOCKS, TPB>>>(yhat, yv, n);
    reduce_kernel<<<1, NBLOCKS>>>((float*)d_out);
}

// round 2
// speedup vs baseline: 1.4785x; 1.4785x over previous
#include <cuda_runtime.h>
#include <math.h>

#define NQ 32
#define NBLOCKS 512
#define TPB 256

// ---- 32-point Gauss-Legendre (positive half; symmetric) ----
__device__ constexpr float GLX16[16] = {
    0.04830766568773832f, 0.14447196158279649f, 0.23928736225213707f, 0.33186860228212765f,
    0.42135127613063535f, 0.50689990893222939f, 0.58771575724076233f, 0.66304426693021520f,
    0.73218211874028968f, 0.79448379596794241f, 0.84936761373256997f, 0.89632115576605212f,
    0.93490607593773969f, 0.96476225558750643f, 0.98561151154526840f, 0.99726386184948156f};
__device__ constexpr float GLW16[16] = {
    0.09654008851472781f, 0.09563872007927486f, 0.09384439908080456f, 0.09117387869576388f,
    0.08765209300440381f, 0.08331192422694676f, 0.07819389578707031f, 0.07234579410884851f,
    0.06582222277636185f, 0.05868409347853555f, 0.05099805926237618f, 0.04283589802222668f,
    0.03427386291302143f, 0.02539206530926206f, 0.01627439473090567f, 0.00701861000947010f};

// hx = (x+1)/2 for node index q in [0,32) (first 16 negative nodes, then positive)
__device__ constexpr float hx_of(int q) {
    return (q < 16) ? 0.5f * (1.0f - GLX16[15 - q]) : 0.5f * (1.0f + GLX16[q - 16]);
}
__device__ constexpr float gw_of(int q) {
    return (q < 16) ? GLW16[15 - q] : GLW16[q - 16];
}

__device__ double d_part[NBLOCKS];
__device__ unsigned int d_count;   // zero-initialized; reset by last block each launch

__device__ __forceinline__ float ex2f(float x) {
    float y;
    asm("ex2.approx.ftz.f32 %0, %1;" : "=f"(y) : "f"(x));
    return y;
}

// Acklam inverse-normal-CDF, central region only (valid 0.02425 < p < 0.97575;
// inputs are guaranteed in (0.05, 0.95)). |rel err| ~1.2e-9 of approximation.
__device__ __forceinline__ float ninv_central(float p) {
    const float q = p - 0.5f;
    const float r = q * q;
    float num = fmaf(-3.969683028665376e+01f, r, 2.209460984245205e+02f);
    num = fmaf(num, r, -2.759285104469687e+02f);
    num = fmaf(num, r, 1.383577518672690e+02f);
    num = fmaf(num, r, -3.066479806614716e+01f);
    num = fmaf(num, r, 2.506628277459239e+00f);
    float den = fmaf(-5.447609879822406e+01f, r, 1.615858368580409e+02f);
    den = fmaf(den, r, -1.556989798598866e+02f);
    den = fmaf(den, r, 6.680131188771972e+01f);
    den = fmaf(den, r, -1.328068155288572e+01f);
    den = fmaf(den, r, 1.0f);
    return q * __fdividef(num, den);
}

__global__ __launch_bounds__(TPB) void loss_kernel(
    const float* __restrict__ yhat, const float* __restrict__ yv,
    const float* __restrict__ g12, const float* __restrict__ g34,
    const float* __restrict__ g3412, const float* __restrict__ s1p,
    const float* __restrict__ s2p, int n, float* __restrict__ out) {
    __shared__ float s_sc[13];
    __shared__ float s_c0[NQ], s_lw[NQ];
    __shared__ double sd[TPB];
    __shared__ int s_last;

    const int tid = threadIdx.x;

    // ---- per-block scalar setup (fp32; ~40 flops) ----
    if (tid == 0) {
        const float a = g12[0], b = g12[1], c = g12[2], d = g12[3];
        const float inv_det = 1.0f / (a * d - b * c);
        const float i00 = d * inv_det, i01 = -b * inv_det;
        const float i10 = -c * inv_det, i11 = a * inv_det;
        const float t0 = g3412[0], t1 = g3412[1], t2 = g3412[2], t3 = g3412[3];
        const float M00 = t0 * i00 + t1 * i10, M01 = t0 * i01 + t1 * i11;
        const float M10 = t2 * i00 + t3 * i10, M11 = t2 * i01 + t3 * i11;
        const float gs00 = g34[0] - (M00 * t0 + M01 * t1);
        const float gs01 = g34[1] - (M00 * t2 + M01 * t3);
        const float gs11 = g34[3] - (M10 * t2 + M11 * t3);
        const float s1g = sqrtf(gs00), s2g = sqrtf(gs11);
        const float rho = gs01 / (s1g * s2g);
        s_sc[0] = M00; s_sc[1] = M01; s_sc[2] = M10; s_sc[3] = M11;
        s_sc[4] = i00; s_sc[5] = i01 + i10; s_sc[6] = i11;
        s_sc[7] = 1.0f / s1g; s_sc[8] = 1.0f / s2g;
        s_sc[9] = (rho >= 0.0f) ? 1.0f : -1.0f;
        s_sc[10] = 1.0f / s1p[0];
        s_sc[11] = 1.0f / s2p[0];
        s_sc[12] = 2.0f * rho;
    }
    __syncthreads();
    if (tid < NQ) {
        const float rho = 0.5f * s_sc[12];
        const float hx = hx_of(tid);
        const float w = gw_of(tid);
        const float r = rho * hx;
        const float omr2 = 1.0f - r * r;
        s_c0[tid] = 1.4426950408889634f / (2.0f * omr2);
        const float amp = w * fabsf(rho) * 0.5f / (6.283185307179586f * sqrtf(omr2));
        s_lw[tid] = __log2f(amp);
    }
    __syncthreads();

    const float M00 = s_sc[0], M01 = s_sc[1], M10 = s_sc[2], M11 = s_sc[3];
    const float i00 = s_sc[4], i01s = s_sc[5], i11 = s_sc[6];
    const float inv_s1g = s_sc[7], inv_s2g = s_sc[8], sgn = s_sc[9];
    const float inv_sig1 = s_sc[10], inv_sig2 = s_sc[11], rho2 = s_sc[12];

    float c0r[NQ], lwr[NQ];
#pragma unroll
    for (int q = 0; q < NQ; q++) { c0r[q] = s_c0[q]; lwr[q] = s_lw[q]; }

    const float* p3p = yhat;
    const float* m1p = yhat + n;
    const float* p4p = yhat + 2 * n;
    const float* m2p = yhat + 3 * n;
    const float* l3p = yv;
    const float* r1p = yv + n;
    const float* l4p = yv + 2 * n;
    const float* r2p = yv + 3 * n;

    float tsum = 0.0f;
    const int stride = gridDim.x * blockDim.x;
    for (int i = blockIdx.x * blockDim.x + tid; i < n; i += stride) {
        const float p3 = __ldg(p3p + i);
        const float p4 = __ldg(p4p + i);
        const float e1 = (__ldg(r1p + i) - __ldg(m1p + i)) * inv_sig1;
        const float e2 = (__ldg(r2p + i) - __ldg(m2p + i)) * inv_sig2;
        const float l3 = __ldg(l3p + i);
        const float l4 = __ldg(l4p + i);

        const float mu1 = fmaf(M00, e1, M01 * e2);
        const float mu2 = fmaf(M10, e1, M11 * e2);
        const float quad = fmaf(i00 * e1, e1, fmaf(i01s * e1, e2, i11 * e2 * e2));

        const float q3 = ninv_central(1.0f - p3);
        const float q4 = ninv_central(1.0f - p4);
        const float h = (q3 - mu1) * inv_s1g;
        const float k = (q4 - mu2) * inv_s2g;
        const float P3 = normcdff(h);
        const float P4 = normcdff(k);

        const float mS = -fmaf(h, h, k * k);     // -(h^2+k^2)
        const float HK = rho2 * h * k;           // 2*rho*h*k

        float acc0 = 0.0f, acc1 = 0.0f;
#pragma unroll
        for (int q = 0; q < NQ; q += 2) {
            const float T0 = fmaf(HK, hx_of(q), mS);
            const float T1 = fmaf(HK, hx_of(q + 1), mS);
            const float E0 = fmaf(c0r[q], T0, lwr[q]);
            const float E1 = fmaf(c0r[q + 1], T1, lwr[q + 1]);
            acc0 += ex2f(E0);
            acc1 += ex2f(E1);
        }
        const float B = fmaf(P3, P4, sgn * (acc0 + acc1));   // BVN(h,k;rho)

        const bool b3 = !(l3 < 1.0f);
        const bool b4 = !(l4 < 1.0f);
        const float Ci = b3 ? (b4 ? (1.0f - P3 - P4 + B) : (P4 - B))
                            : (b4 ? (P3 - B) : B);

        tsum += fmaf(-0.5f, quad, __logf(fmaxf(Ci, 1e-30f)));
    }

    // ---- deterministic block reduction ----
    sd[tid] = (double)tsum;
    __syncthreads();
#pragma unroll
    for (int s = TPB / 2; s > 0; s >>= 1) {
        if (tid < s) sd[tid] += sd[tid + s];
        __syncthreads();
    }
    if (tid == 0) {
        d_part[blockIdx.x] = sd[0];
        __threadfence();
        const unsigned int old = atomicAdd(&d_count, 1u);
        s_last = (old == gridDim.x - 1) ? 1 : 0;
    }
    __syncthreads();

    // ---- last block: deterministic final reduction ----
    if (s_last) {
        double v = 0.0;
        for (int j = tid; j < NBLOCKS; j += TPB) v += d_part[j];
        sd[tid] = v;
        __syncthreads();
#pragma unroll
        for (int s = TPB / 2; s > 0; s >>= 1) {
            if (tid < s) sd[tid] += sd[tid + s];
            __syncthreads();
        }
        if (tid == 0) {
            out[0] = (float)(-sd[0]);
            d_count = 0;   // reset for next graph replay
        }
    }
}

extern "C" void kernel_launch(void* const* d_in, const int* in_sizes, int n_in,
                              void* d_out, int out_size) {
    const float* yhat = (const float*)d_in[0];
    const float* yv = (const float*)d_in[1];
    const float* g12 = (const float*)d_in[2];
    const float* g34 = (const float*)d_in[3];
    const float* g3412 = (const float*)d_in[4];
    const float* s1 = (const float*)d_in[5];
    const float* s2 = (const float*)d_in[6];
    const int n = in_sizes[0] / 4;

    loss_kernel<<<NBLOCKS, TPB>>>(yhat, yv, g12, g34, g3412, s1, s2, n, (float*)d_out);
}

// round 3
// speedup vs baseline: 2.2896x; 1.5486x over previous
#include <cuda_runtime.h>
#include <math.h>

#define NQ 16
#define NBLOCKS 592
#define TPB 256

// ---- 16-point Gauss-Legendre (positive half; symmetric) ----
__device__ constexpr float GLX8[8] = {
    0.09501250983763744f, 0.28160355077925891f, 0.45801677765722739f, 0.61787624440264375f,
    0.75540440835500303f, 0.86563120238783174f, 0.94457502307323258f, 0.98940093499164993f};
__device__ constexpr float GLW8[8] = {
    0.18945061045506850f, 0.18260341504492359f, 0.16915651939500254f, 0.14959598881657673f,
    0.12462897125553387f, 0.09515851168249278f, 0.06225352393864789f, 0.02715245941175409f};

// hx = (x+1)/2 for node index q in [0,16) (first 8 negative nodes, then positive)
__device__ constexpr float hx_of(int q) {
    return (q < 8) ? 0.5f * (1.0f - GLX8[7 - q]) : 0.5f * (1.0f + GLX8[q - 8]);
}
__device__ constexpr float gw_of(int q) {
    return (q < 8) ? GLW8[7 - q] : GLW8[q - 8];
}

__device__ double d_part[NBLOCKS];
__device__ unsigned int d_count;   // zero-initialized; reset by last block each launch

__device__ __forceinline__ float ex2f(float x) {
    float y;
    asm("ex2.approx.ftz.f32 %0, %1;" : "=f"(y) : "f"(x));
    return y;
}
__device__ __forceinline__ float rcpf(float x) {
    float y;
    asm("rcp.approx.ftz.f32 %0, %1;" : "=f"(y) : "f"(x));
    return y;
}

// Acklam inverse-normal-CDF, central region only (inputs in (0.05, 0.95)).
__device__ __forceinline__ float ninv_central(float p) {
    const float q = p - 0.5f;
    const float r = q * q;
    float num = fmaf(-3.969683028665376e+01f, r, 2.209460984245205e+02f);
    num = fmaf(num, r, -2.759285104469687e+02f);
    num = fmaf(num, r, 1.383577518672690e+02f);
    num = fmaf(num, r, -3.066479806614716e+01f);
    num = fmaf(num, r, 2.506628277459239e+00f);
    float den = fmaf(-5.447609879822406e+01f, r, 1.615858368580409e+02f);
    den = fmaf(den, r, -1.556989798598866e+02f);
    den = fmaf(den, r, 6.680131188771972e+01f);
    den = fmaf(den, r, -1.328068155288572e+01f);
    den = fmaf(den, r, 1.0f);
    return q * num * rcpf(den);
}

// Phi(h) via A&S 7.1.26 erfc (abs err <= 1.5e-7). h2g = h*h*(-log2e/2), precomputed.
__device__ __forceinline__ float phi_fast(float h, float eneg) {
    // eneg = exp(-h^2/2) supplied as ex2 of precomputed exponent
    const float z = fabsf(h) * 0.70710678118654752f;   // |h|/sqrt(2)
    const float t = rcpf(fmaf(0.3275911f, z, 1.0f));
    float poly = fmaf(1.061405429f, t, -1.453152027f);
    poly = fmaf(poly, t, 1.421413741f);
    poly = fmaf(poly, t, -0.284496736f);
    poly = fmaf(poly, t, 0.254829592f);
    const float half_erfc = 0.5f * poly * t * eneg;    // 0.5*erfc(z)
    return (h >= 0.0f) ? (1.0f - half_erfc) : half_erfc;
}

__global__ __launch_bounds__(TPB, 4) void loss_kernel(
    const float* __restrict__ yhat, const float* __restrict__ yv,
    const float* __restrict__ g12, const float* __restrict__ g34,
    const float* __restrict__ g3412, const float* __restrict__ s1p,
    const float* __restrict__ s2p, int n, float* __restrict__ out) {
    __shared__ float s_sc[13];
    __shared__ float2 s_cw[NQ];          // (c0, lw) per node
    __shared__ double sd[TPB];
    __shared__ int s_last;

    const int tid = threadIdx.x;

    if (tid == 0) {
        const float a = g12[0], b = g12[1], c = g12[2], d = g12[3];
        const float inv_det = 1.0f / (a * d - b * c);
        const float i00 = d * inv_det, i01 = -b * inv_det;
        const float i10 = -c * inv_det, i11 = a * inv_det;
        const float t0 = g3412[0], t1 = g3412[1], t2 = g3412[2], t3 = g3412[3];
        const float M00 = t0 * i00 + t1 * i10, M01 = t0 * i01 + t1 * i11;
        const float M10 = t2 * i00 + t3 * i10, M11 = t2 * i01 + t3 * i11;
        const float gs00 = g34[0] - (M00 * t0 + M01 * t1);
        const float gs01 = g34[1] - (M00 * t2 + M01 * t3);
        const float gs11 = g34[3] - (M10 * t2 + M11 * t3);
        const float s1g = sqrtf(gs00), s2g = sqrtf(gs11);
        const float rho = gs01 / (s1g * s2g);
        s_sc[0] = M00; s_sc[1] = M01; s_sc[2] = M10; s_sc[3] = M11;
        s_sc[4] = i00; s_sc[5] = i01 + i10; s_sc[6] = i11;
        s_sc[7] = 1.0f / s1g; s_sc[8] = 1.0f / s2g;
        s_sc[9] = (rho >= 0.0f) ? 1.0f : -1.0f;
        s_sc[10] = 1.0f / s1p[0];
        s_sc[11] = 1.0f / s2p[0];
        s_sc[12] = 2.0f * rho;
    }
    __syncthreads();
    if (tid < NQ) {
        const float rho = 0.5f * s_sc[12];
        const float hx = hx_of(tid);
        const float w = gw_of(tid);
        const float r = rho * hx;
        const float omr2 = 1.0f - r * r;
        float2 cw;
        cw.x = 1.4426950408889634f / (2.0f * omr2);
        const float amp = w * fabsf(rho) * 0.5f / (6.283185307179586f * sqrtf(omr2));
        cw.y = __log2f(amp);
        s_cw[tid] = cw;
    }
    __syncthreads();

    const float M00 = s_sc[0], M01 = s_sc[1], M10 = s_sc[2], M11 = s_sc[3];
    const float i00 = s_sc[4], i01s = s_sc[5], i11 = s_sc[6];
    const float inv_s1g = s_sc[7], inv_s2g = s_sc[8], sgn = s_sc[9];
    const float inv_sig1 = s_sc[10], inv_sig2 = s_sc[11], rho2 = s_sc[12];

    const float* p3p = yhat;
    const float* m1p = yhat + n;
    const float* p4p = yhat + 2 * n;
    const float* m2p = yhat + 3 * n;
    const float* l3p = yv;
    const float* r1p = yv + n;
    const float* l4p = yv + 2 * n;
    const float* r2p = yv + 3 * n;

    float tsum = 0.0f;
    const int stride = gridDim.x * blockDim.x;
    for (int i = blockIdx.x * blockDim.x + tid; i < n; i += stride) {
        const float p3 = __ldg(p3p + i);
        const float p4 = __ldg(p4p + i);
        const float e1 = (__ldg(r1p + i) - __ldg(m1p + i)) * inv_sig1;
        const float e2 = (__ldg(r2p + i) - __ldg(m2p + i)) * inv_sig2;
        const float l3 = __ldg(l3p + i);
        const float l4 = __ldg(l4p + i);

        const float mu1 = fmaf(M00, e1, M01 * e2);
        const float mu2 = fmaf(M10, e1, M11 * e2);
        const float quad = fmaf(i00 * e1, e1, fmaf(i01s * e1, e2, i11 * e2 * e2));

        const float q3 = ninv_central(1.0f - p3);
        const float q4 = ninv_central(1.0f - p4);
        const float h = (q3 - mu1) * inv_s1g;
        const float k = (q4 - mu2) * inv_s2g;

        const float h2 = h * h;
        const float k2 = k * k;
        // exp(-h^2/2), exp(-k^2/2) — shared by Phi and available cheaply
        const float eh = ex2f(-0.72134752044448170f * h2);
        const float ek = ex2f(-0.72134752044448170f * k2);
        const float P3 = phi_fast(h, eh);
        const float P4 = phi_fast(k, ek);

        const float mS = -(h2 + k2);             // -(h^2+k^2)
        const float HK = rho2 * h * k;           // 2*rho*h*k

        float acc0 = 0.0f, acc1 = 0.0f;
#pragma unroll
        for (int q = 0; q < NQ; q += 2) {
            const float2 cw0 = s_cw[q];
            const float2 cw1 = s_cw[q + 1];
            const float T0 = fmaf(HK, hx_of(q), mS);
            const float T1 = fmaf(HK, hx_of(q + 1), mS);
            acc0 += ex2f(fmaf(cw0.x, T0, cw0.y));
            acc1 += ex2f(fmaf(cw1.x, T1, cw1.y));
        }
        const float B = fmaf(P3, P4, sgn * (acc0 + acc1));   // BVN(h,k;rho)

        const bool b3 = !(l3 < 1.0f);
        const bool b4 = !(l4 < 1.0f);
        const float Ci = b3 ? (b4 ? (1.0f - P3 - P4 + B) : (P4 - B))
                            : (b4 ? (P3 - B) : B);

        tsum += fmaf(-0.5f, quad, __logf(fmaxf(Ci, 1e-30f)));
    }

    // ---- deterministic block reduction ----
    sd[tid] = (double)tsum;
    __syncthreads();
#pragma unroll
    for (int s = TPB / 2; s > 0; s >>= 1) {
        if (tid < s) sd[tid] += sd[tid + s];
        __syncthreads();
    }
    if (tid == 0) {
        d_part[blockIdx.x] = sd[0];
        __threadfence();
        const unsigned int old = atomicAdd(&d_count, 1u);
        s_last = (old == gridDim.x - 1) ? 1 : 0;
    }
    __syncthreads();

    // ---- last block: deterministic final reduction ----
    if (s_last) {
        double v = 0.0;
        for (int j = tid; j < NBLOCKS; j += TPB) v += d_part[j];
        sd[tid] = v;
        __syncthreads();
#pragma unroll
        for (int s = TPB / 2; s > 0; s >>= 1) {
            if (tid < s) sd[tid] += sd[tid + s];
            __syncthreads();
        }
        if (tid == 0) {
            out[0] = (float)(-sd[0]);
            d_count = 0;   // reset for next graph replay
        }
    }
}

extern "C" void kernel_launch(void* const* d_in, const int* in_sizes, int n_in,
                              void* d_out, int out_size) {
    const float* yhat = (const float*)d_in[0];
    const float* yv = (const float*)d_in[1];
    const float* g12 = (const float*)d_in[2];
    const float* g34 = (const float*)d_in[3];
    const float* g3412 = (const float*)d_in[4];
    const float* s1 = (const float*)d_in[5];
    const float* s2 = (const float*)d_in[6];
    const int n = in_sizes[0] / 4;

    loss_kernel<<<NBLOCKS, TPB>>>(yhat, yv, g12, g34, g3412, s1, s2, n, (float*)d_out);
}

// round 4
// speedup vs baseline: 2.6250x; 1.1465x over previous
#include <cuda_runtime.h>
#include <math.h>

#define NQ 8
#define NBLOCKS 592
#define TPB 256

// ---- 8-point Gauss-Legendre (positive half; symmetric) ----
__device__ constexpr float GLX4[4] = {
    0.18343464249564980f, 0.52553240991632899f, 0.79666647741362674f, 0.96028985649753623f};
__device__ constexpr float GLW4[4] = {
    0.36268378337836198f, 0.31370664587788729f, 0.22238103445337447f, 0.10122853629037626f};

// hx = (x+1)/2 for node index q in [0,8) (first 4 negative nodes, then positive)
__device__ constexpr float hx_of(int q) {
    return (q < 4) ? 0.5f * (1.0f - GLX4[3 - q]) : 0.5f * (1.0f + GLX4[q - 4]);
}
__device__ constexpr float gw_of(int q) {
    return (q < 4) ? GLW4[3 - q] : GLW4[q - 4];
}

__device__ double d_part[NBLOCKS];
__device__ unsigned int d_count;   // zero-init; reset by last block each launch

__device__ __forceinline__ float ex2f(float x) {
    float y;
    asm("ex2.approx.ftz.f32 %0, %1;" : "=f"(y) : "f"(x));
    return y;
}
__device__ __forceinline__ float rcpf(float x) {
    float y;
    asm("rcp.approx.ftz.f32 %0, %1;" : "=f"(y) : "f"(x));
    return y;
}

// Acklam inverse-normal-CDF, central region (inputs in (0.05, 0.95)).
__device__ __forceinline__ float ninv_central(float p) {
    const float q = p - 0.5f;
    const float r = q * q;
    float num = fmaf(-3.969683028665376e+01f, r, 2.209460984245205e+02f);
    num = fmaf(num, r, -2.759285104469687e+02f);
    num = fmaf(num, r, 1.383577518672690e+02f);
    num = fmaf(num, r, -3.066479806614716e+01f);
    num = fmaf(num, r, 2.506628277459239e+00f);
    float den = fmaf(-5.447609879822406e+01f, r, 1.615858368580409e+02f);
    den = fmaf(den, r, -1.556989798598866e+02f);
    den = fmaf(den, r, 6.680131188771972e+01f);
    den = fmaf(den, r, -1.328068155288572e+01f);
    den = fmaf(den, r, 1.0f);
    return q * num * rcpf(den);
}

// Phi(h) via A&S 7.1.26 erfc (abs err <= 1.5e-7); eneg = exp(-h^2/2).
__device__ __forceinline__ float phi_fast(float h, float eneg) {
    const float z = fabsf(h) * 0.70710678118654752f;
    const float t = rcpf(fmaf(0.3275911f, z, 1.0f));
    float poly = fmaf(1.061405429f, t, -1.453152027f);
    poly = fmaf(poly, t, 1.421413741f);
    poly = fmaf(poly, t, -0.284496736f);
    poly = fmaf(poly, t, 0.254829592f);
    const float half_erfc = 0.5f * poly * t * eneg;
    return (h >= 0.0f) ? (1.0f - half_erfc) : half_erfc;
}

__global__ __launch_bounds__(TPB, 4) void loss_kernel(
    const float* __restrict__ yhat, const float* __restrict__ yv,
    const float* __restrict__ g12, const float* __restrict__ g34,
    const float* __restrict__ g3412, const float* __restrict__ s1p,
    const float* __restrict__ s2p, int n, float* __restrict__ out) {
    __shared__ float s_sc[13];
    __shared__ float2 s_cw[NQ];
    __shared__ double sd[TPB];
    __shared__ int s_last;

    const int tid = threadIdx.x;

    if (tid == 0) {
        const float a = g12[0], b = g12[1], c = g12[2], d = g12[3];
        const float inv_det = 1.0f / (a * d - b * c);
        const float i00 = d * inv_det, i01 = -b * inv_det;
        const float i10 = -c * inv_det, i11 = a * inv_det;
        const float t0 = g3412[0], t1 = g3412[1], t2 = g3412[2], t3 = g3412[3];
        const float M00 = t0 * i00 + t1 * i10, M01 = t0 * i01 + t1 * i11;
        const float M10 = t2 * i00 + t3 * i10, M11 = t2 * i01 + t3 * i11;
        const float gs00 = g34[0] - (M00 * t0 + M01 * t1);
        const float gs01 = g34[1] - (M00 * t2 + M01 * t3);
        const float gs11 = g34[3] - (M10 * t2 + M11 * t3);
        const float s1g = sqrtf(gs00), s2g = sqrtf(gs11);
        const float rho = gs01 / (s1g * s2g);
        s_sc[0] = M00; s_sc[1] = M01; s_sc[2] = M10; s_sc[3] = M11;
        s_sc[4] = i00; s_sc[5] = i01 + i10; s_sc[6] = i11;
        s_sc[7] = 1.0f / s1g; s_sc[8] = 1.0f / s2g;
        s_sc[9] = (rho >= 0.0f) ? 1.0f : -1.0f;
        s_sc[10] = 1.0f / s1p[0];
        s_sc[11] = 1.0f / s2p[0];
        s_sc[12] = 2.0f * rho;
    }
    __syncthreads();
    if (tid < NQ) {
        const float rho = 0.5f * s_sc[12];
        const float hx = hx_of(tid);
        const float w = gw_of(tid);
        const float r = rho * hx;
        const float omr2 = 1.0f - r * r;
        float2 cw;
        cw.x = 1.4426950408889634f / (2.0f * omr2);
        const float amp = w * fabsf(rho) * 0.5f / (6.283185307179586f * sqrtf(omr2));
        cw.y = __log2f(amp);
        s_cw[tid] = cw;
    }
    __syncthreads();

    const float M00 = s_sc[0], M01 = s_sc[1], M10 = s_sc[2], M11 = s_sc[3];
    const float i00 = s_sc[4], i01s = s_sc[5], i11 = s_sc[6];
    const float inv_s1g = s_sc[7], inv_s2g = s_sc[8], sgn = s_sc[9];
    const float inv_sig1 = s_sc[10], inv_sig2 = s_sc[11], rho2 = s_sc[12];

    const int half = n >> 1;
    const float2* p3p = (const float2*)yhat;
    const float2* m1p = (const float2*)(yhat + n);
    const float2* p4p = (const float2*)(yhat + 2 * n);
    const float2* m2p = (const float2*)(yhat + 3 * n);
    const float2* l3p = (const float2*)yv;
    const float2* r1p = (const float2*)(yv + n);
    const float2* l4p = (const float2*)(yv + 2 * n);
    const float2* r2p = (const float2*)(yv + 3 * n);

    float tsum = 0.0f;
    const int gid = blockIdx.x * blockDim.x + tid;
    const int stride = gridDim.x * blockDim.x;
    for (int i = gid; i < half; i += stride) {
        const float2 p3 = __ldg(p3p + i);
        const float2 p4 = __ldg(p4p + i);
        const float2 m1 = __ldg(m1p + i);
        const float2 m2 = __ldg(m2p + i);
        const float2 l3 = __ldg(l3p + i);
        const float2 l4 = __ldg(l4p + i);
        const float2 r1 = __ldg(r1p + i);
        const float2 r2 = __ldg(r2p + i);

        // ---- lane a ----
        const float e1a = (r1.x - m1.x) * inv_sig1;
        const float e2a = (r2.x - m2.x) * inv_sig2;
        const float mu1a = fmaf(M00, e1a, M01 * e2a);
        const float mu2a = fmaf(M10, e1a, M11 * e2a);
        const float quada = fmaf(i00 * e1a, e1a, fmaf(i01s * e1a, e2a, i11 * e2a * e2a));
        const float ha = (ninv_central(1.0f - p3.x) - mu1a) * inv_s1g;
        const float ka = (ninv_central(1.0f - p4.x) - mu2a) * inv_s2g;
        const float h2a = ha * ha, k2a = ka * ka;
        const float eha = ex2f(-0.72134752044448170f * h2a);
        const float eka = ex2f(-0.72134752044448170f * k2a);
        const float P3a = phi_fast(ha, eha);
        const float P4a = phi_fast(ka, eka);
        const float mSa = -(h2a + k2a);
        const float HKa = rho2 * ha * ka;

        // ---- lane b ----
        const float e1b = (r1.y - m1.y) * inv_sig1;
        const float e2b = (r2.y - m2.y) * inv_sig2;
        const float mu1b = fmaf(M00, e1b, M01 * e2b);
        const float mu2b = fmaf(M10, e1b, M11 * e2b);
        const float quadb = fmaf(i00 * e1b, e1b, fmaf(i01s * e1b, e2b, i11 * e2b * e2b));
        const float hb = (ninv_central(1.0f - p3.y) - mu1b) * inv_s1g;
        const float kb = (ninv_central(1.0f - p4.y) - mu2b) * inv_s2g;
        const float h2b = hb * hb, k2b = kb * kb;
        const float ehb = ex2f(-0.72134752044448170f * h2b);
        const float ekb = ex2f(-0.72134752044448170f * k2b);
        const float P3b = phi_fast(hb, ehb);
        const float P4b = phi_fast(kb, ekb);
        const float mSb = -(h2b + k2b);
        const float HKb = rho2 * hb * kb;

        // ---- fused quadrature: both lanes share the node constants ----
        float a0 = 0.0f, a1 = 0.0f, b0 = 0.0f, b1 = 0.0f;
#pragma unroll
        for (int q = 0; q < NQ; q += 2) {
            const float2 cw0 = s_cw[q];
            const float2 cw1 = s_cw[q + 1];
            a0 += ex2f(fmaf(cw0.x, fmaf(HKa, hx_of(q), mSa), cw0.y));
            b0 += ex2f(fmaf(cw0.x, fmaf(HKb, hx_of(q), mSb), cw0.y));
            a1 += ex2f(fmaf(cw1.x, fmaf(HKa, hx_of(q + 1), mSa), cw1.y));
            b1 += ex2f(fmaf(cw1.x, fmaf(HKb, hx_of(q + 1), mSb), cw1.y));
        }
        const float Ba = fmaf(P3a, P4a, sgn * (a0 + a1));
        const float Bb = fmaf(P3b, P4b, sgn * (b0 + b1));

        const bool b3a = !(l3.x < 1.0f), b4a = !(l4.x < 1.0f);
        const float Cia = b3a ? (b4a ? (1.0f - P3a - P4a + Ba) : (P4a - Ba))
                              : (b4a ? (P3a - Ba) : Ba);
        const bool b3b = !(l3.y < 1.0f), b4b = !(l4.y < 1.0f);
        const float Cib = b3b ? (b4b ? (1.0f - P3b - P4b + Bb) : (P4b - Bb))
                              : (b4b ? (P3b - Bb) : Bb);

        tsum += fmaf(-0.5f, quada, __logf(fmaxf(Cia, 1e-30f)));
        tsum += fmaf(-0.5f, quadb, __logf(fmaxf(Cib, 1e-30f)));
    }

    // odd-n tail: one scalar element handled by global thread 0
    if ((n & 1) && gid == 0) {
        const int i = n - 1;
        const float e1 = (yv[n + i] - yhat[n + i]) * inv_sig1;
        const float e2 = (yv[3 * n + i] - yhat[3 * n + i]) * inv_sig2;
        const float mu1 = fmaf(M00, e1, M01 * e2);
        const float mu2 = fmaf(M10, e1, M11 * e2);
        const float quad = fmaf(i00 * e1, e1, fmaf(i01s * e1, e2, i11 * e2 * e2));
        const float h = (ninv_central(1.0f - yhat[i]) - mu1) * inv_s1g;
        const float k = (ninv_central(1.0f - yhat[2 * n + i]) - mu2) * inv_s2g;
        const float h2 = h * h, k2 = k * k;
        const float P3 = phi_fast(h, ex2f(-0.72134752044448170f * h2));
        const float P4 = phi_fast(k, ex2f(-0.72134752044448170f * k2));
        const float mS = -(h2 + k2);
        const float HK = rho2 * h * k;
        float acc = 0.0f;
#pragma unroll
        for (int q = 0; q < NQ; q++) {
            const float2 cw = s_cw[q];
            acc += ex2f(fmaf(cw.x, fmaf(HK, hx_of(q), mS), cw.y));
        }
        const float B = fmaf(P3, P4, sgn * acc);
        const bool b3 = !(yv[i] < 1.0f), b4 = !(yv[2 * n + i] < 1.0f);
        const float Ci = b3 ? (b4 ? (1.0f - P3 - P4 + B) : (P4 - B))
                            : (b4 ? (P3 - B) : B);
        tsum += fmaf(-0.5f, quad, __logf(fmaxf(Ci, 1e-30f)));
    }

    // ---- deterministic block reduction ----
    sd[tid] = (double)tsum;
    __syncthreads();
#pragma unroll
    for (int s = TPB / 2; s > 0; s >>= 1) {
        if (tid < s) sd[tid] += sd[tid + s];
        __syncthreads();
    }
    if (tid == 0) {
        d_part[blockIdx.x] = sd[0];
        __threadfence();
        const unsigned int old = atomicAdd(&d_count, 1u);
        s_last = (old == gridDim.x - 1) ? 1 : 0;
    }
    __syncthreads();

    if (s_last) {
        double v = 0.0;
        for (int j = tid; j < NBLOCKS; j += TPB) v += d_part[j];
        sd[tid] = v;
        __syncthreads();
#pragma unroll
        for (int s = TPB / 2; s > 0; s >>= 1) {
            if (tid < s) sd[tid] += sd[tid + s];
            __syncthreads();
        }
        if (tid == 0) {
            out[0] = (float)(-sd[0]);
            d_count = 0;
        }
    }
}

extern "C" void kernel_launch(void* const* d_in, const int* in_sizes, int n_in,
                              void* d_out, int out_size) {
    const float* yhat = (const float*)d_in[0];
    const float* yv = (const float*)d_in[1];
    const float* g12 = (const float*)d_in[2];
    const float* g34 = (const float*)d_in[3];
    const float* g3412 = (const float*)d_in[4];
    const float* s1 = (const float*)d_in[5];
    const float* s2 = (const float*)d_in[6];
    const int n = in_sizes[0] / 4;

    loss_kernel<<<NBLOCKS, TPB>>>(yhat, yv, g12, g34, g3412, s1, s2, n, (float*)d_out);
}